// round 15
// baseline (speedup 1.0000x reference)
#include <cuda_runtime.h>
#include <cuda_bf16.h>
#include <cuda_fp16.h>
#include <math.h>
#include <stdint.h>

// ---------------- problem constants ----------------
#define Bn   4
#define Ln   4096
#define Hn   4
#define Dn   256
#define Pn   1024
#define Cn   64
#define NCn  64
#define BHn  16
#define ROWS (Bn*Ln)            // 16384
#define ELEMS (ROWS*Pn)         // 16777216

// ---------------- device scratch (static, no runtime alloc) ----------------
__device__ float g_U[ELEMS];     // U = T' @ V   (b,h,l,d)
__device__ float g_beta[BHn*Ln];
__device__ float g_o[ELEMS];     // scan output (b,h,l,d)

// fp16 projection outputs (written directly by QKV GEMM)
__device__ __half g_qlinh[ELEMS];
__device__ __half g_klinh[ELEMS];
__device__ __half g_vlinh[ELEMS];

// fp16 split operands for the big GEMMs
__device__ __half g_xh[ELEMS];
__device__ __half g_xl[ELEMS];
__device__ __half g_onh[ELEMS];
__device__ __half g_onl[ELEMS];
__device__ __half g_wT[8][1024*1024];

// fp16 split operands for scan/prep tensor-core work
__device__ __half g_Wbh[ELEMS];
__device__ __half g_Wbl[ELEMS];
__device__ __half g_Qbh[ELEMS];
__device__ __half g_Qbl[ELEMS];
__device__ __half g_Kbh[ELEMS];
__device__ __half g_Kbl[ELEMS];
__device__ __half g_Vbh[ELEMS];
__device__ __half g_Gbh[BHn*NCn*Cn*Cn];
__device__ __half g_Gbl[BHn*NCn*Cn*Cn];

// =====================================================================
// helpers
// =====================================================================
__device__ __forceinline__ uint32_t smem_u32(const void* p){
    uint32_t a;
    asm("{ .reg .u64 t; cvta.to.shared.u64 t, %1; cvt.u32.u64 %0, t; }" : "=r"(a) : "l"(p));
    return a;
}
__device__ __forceinline__ void cp_async16(uint32_t dst, const void* src){
    asm volatile("cp.async.cg.shared.global [%0], [%1], 16;" :: "r"(dst), "l"(src) : "memory");
}
__device__ __forceinline__ void cp_commit(){ asm volatile("cp.async.commit_group;" ::: "memory"); }
template<int N> __device__ __forceinline__ void cp_wait(){ asm volatile("cp.async.wait_group %0;" :: "n"(N) : "memory"); }

__device__ __forceinline__ void ldsm_x4(uint32_t* r, uint32_t addr){
    asm volatile("ldmatrix.sync.aligned.m8n8.x4.shared.b16 {%0,%1,%2,%3}, [%4];"
        : "=r"(r[0]), "=r"(r[1]), "=r"(r[2]), "=r"(r[3]) : "r"(addr));
}
__device__ __forceinline__ void ldsm_x4_t(uint32_t* r, uint32_t addr){
    asm volatile("ldmatrix.sync.aligned.m8n8.x4.trans.shared.b16 {%0,%1,%2,%3}, [%4];"
        : "=r"(r[0]), "=r"(r[1]), "=r"(r[2]), "=r"(r[3]) : "r"(addr));
}
// fp16 mma, fp32 acc
__device__ __forceinline__ void mma16816_hf32(float* c, const uint32_t* a, uint32_t b0, uint32_t b1){
    asm volatile(
        "mma.sync.aligned.m16n8k16.row.col.f32.f16.f16.f32 "
        "{%0,%1,%2,%3}, {%4,%5,%6,%7}, {%8,%9}, {%0,%1,%2,%3};"
        : "+f"(c[0]), "+f"(c[1]), "+f"(c[2]), "+f"(c[3])
        : "r"(a[0]), "r"(a[1]), "r"(a[2]), "r"(a[3]), "r"(b0), "r"(b1));
}

__device__ __forceinline__ void split2h(float a, float b, uint32_t& ho, uint32_t& lo){
    __half ha = __float2half_rn(a), hb = __float2half_rn(b);
    float la = a - __half2float(ha);
    float lb = b - __half2float(hb);
    __half2 hv; hv.x = ha; hv.y = hb;
    __half2 lv; lv.x = __float2half_rn(la); lv.y = __float2half_rn(lb);
    ho = *(uint32_t*)&hv; lo = *(uint32_t*)&lv;
}
__device__ __forceinline__ uint32_t pack2h(float a, float b){
    __half2 hv; hv.x = __float2half_rn(a); hv.y = __float2half_rn(b);
    return *(uint32_t*)&hv;
}
__device__ __forceinline__ float4 ld4h(const __half* p){
    uint2 t = *(const uint2*)p;
    __half2 a = *(__half2*)&t.x, b = *(__half2*)&t.y;
    float2 fa = __half22float2(a), fb = __half22float2(b);
    float4 r; r.x = fa.x; r.y = fa.y; r.z = fb.x; r.w = fb.y;
    return r;
}

// =====================================================================
// fp16 2-pass GEMM mainloop (shared)
// =====================================================================
#define NKT2 32
#define P2   80
#define OPB2 (128*P2)
#define STG2 (3*OPB2)
#define GEMM_SMEM (2*STG2 + 128)

__device__ __forceinline__ void g_load_stage2(
    uint32_t sbase, int s, int kt,
    const __half* __restrict__ Ah, const __half* __restrict__ Al,
    const __half* __restrict__ Bh,
    int mBase, int nBase, int tid)
{
    uint32_t sb = sbase + (uint32_t)s * STG2;
    int kofs = kt * 32;
    #pragma unroll
    for (int i = 0; i < 6; i++){
        int flat = tid + i*256;
        int op   = flat >> 9;
        int idx  = flat & 511;
        int row  = idx >> 2;
        int ch   = idx & 3;
        uint32_t d = sb + (uint32_t)(op*OPB2 + row*P2 + ch*16);
        const __half* src;
        size_t g;
        if (op == 0){ src = Ah; g = (size_t)(mBase + row)*1024 + kofs + ch*8; }
        else if (op == 1){ src = Al; g = (size_t)(mBase + row)*1024 + kofs + ch*8; }
        else { src = Bh; g = (size_t)(nBase + row)*1024 + kofs + ch*8; }
        cp_async16(d, src + g);
    }
}

__device__ __forceinline__ void gemm_mainloop(
    uint32_t sbase,
    const __half* __restrict__ Ah, const __half* __restrict__ Al,
    const __half* __restrict__ Bh,
    int mBase, int nBase, int tid, int wid, int lane,
    float acc[4][4][4])
{
    int wm = wid >> 2;
    int wn = wid & 3;
    #pragma unroll
    for (int i=0;i<4;i++)
        #pragma unroll
        for (int j=0;j<4;j++)
            #pragma unroll
            for (int q=0;q<4;q++) acc[i][j][q] = 0.f;

    uint32_t aOff = (uint32_t)((wm*64 + (lane & 15))*P2 + ((lane >> 4) << 4));
    uint32_t bOff = (uint32_t)(2*OPB2 + (wn*32 + (lane & 7) + ((lane >> 4) << 3))*P2
                               + (((lane >> 3) & 1) << 4));

    g_load_stage2(sbase, 0, 0, Ah, Al, Bh, mBase, nBase, tid); cp_commit();

    for (int kt = 0; kt < NKT2; ++kt){
        if (kt + 1 < NKT2)
            g_load_stage2(sbase, (kt+1)&1, kt+1, Ah, Al, Bh, mBase, nBase, tid);
        cp_commit();
        cp_wait<1>();
        __syncthreads();

        uint32_t sb = sbase + (uint32_t)(kt & 1) * STG2;
        #pragma unroll
        for (int ks = 0; ks < 2; ++ks){
            uint32_t bb = sb + bOff + (uint32_t)(ks*32);
            uint32_t bh0[4], bh1[4];
            ldsm_x4(bh0, bb);
            ldsm_x4(bh1, bb + 16*P2);
            #pragma unroll
            for (int im = 0; im < 4; im++){
                uint32_t aa = sb + aOff + (uint32_t)(im*16*P2 + ks*32);
                uint32_t ah[4], al[4];
                ldsm_x4(ah, aa);
                ldsm_x4(al, aa + OPB2);
                #pragma unroll
                for (int in = 0; in < 4; in++){
                    const uint32_t* bhp = (in < 2) ? bh0 : bh1;
                    int j = (in & 1)*2;
                    mma16816_hf32(acc[im][in], ah, bhp[j], bhp[j+1]);
                    mma16816_hf32(acc[im][in], al, bhp[j], bhp[j+1]);
                }
            }
        }
        __syncthreads();
    }
}

// QKV triple GEMM: grid (8, 128, 3); fp16 output
__global__ __launch_bounds__(256, 2) void gemm_qkv(
    const __half* __restrict__ Ah, const __half* __restrict__ Al,
    const __half* __restrict__ B0, const __half* __restrict__ B1,
    const __half* __restrict__ B2,
    __half* __restrict__ C0, __half* __restrict__ C1, __half* __restrict__ C2)
{
    extern __shared__ char dsm[];
    uint32_t sbase = (smem_u32(dsm) + 127u) & ~127u;
    int tid = threadIdx.x, wid = tid >> 5, lane = tid & 31;
    int mBase = blockIdx.y * 128;
    int nBase = blockIdx.x * 128;
    int z = blockIdx.z;
    const __half* Bh = (z == 0) ? B0 : (z == 1) ? B1 : B2;
    __half* C = (z == 0) ? C0 : (z == 1) ? C1 : C2;

    float acc[4][4][4];
    gemm_mainloop(sbase, Ah, Al, Bh, mBase, nBase, tid, wid, lane, acc);

    int wm = wid >> 2, wn = wid & 3;
    #pragma unroll
    for (int im = 0; im < 4; im++){
        int r0 = mBase + wm*64 + im*16 + (lane >> 2);
        #pragma unroll
        for (int in = 0; in < 4; in++){
            int c0 = nBase + wn*32 + in*8 + (lane & 3)*2;
            *(uint32_t*)&C[(size_t)r0*1024 + c0]     = pack2h(acc[im][in][0], acc[im][in][1]);
            *(uint32_t*)&C[(size_t)(r0+8)*1024 + c0] = pack2h(acc[im][in][2], acc[im][in][3]);
        }
    }
}

// Wo GEMM: fp32 output
__global__ __launch_bounds__(256, 2) void gemm_out(
    const __half* __restrict__ Ah, const __half* __restrict__ Al,
    const __half* __restrict__ Bh,
    float* __restrict__ C)
{
    extern __shared__ char dsm[];
    uint32_t sbase = (smem_u32(dsm) + 127u) & ~127u;
    int tid = threadIdx.x, wid = tid >> 5, lane = tid & 31;
    int mBase = blockIdx.y * 128;
    int nBase = blockIdx.x * 128;

    float acc[4][4][4];
    gemm_mainloop(sbase, Ah, Al, Bh, mBase, nBase, tid, wid, lane, acc);

    int wm = wid >> 2, wn = wid & 3;
    #pragma unroll
    for (int im = 0; im < 4; im++){
        int r0 = mBase + wm*64 + im*16 + (lane >> 2);
        #pragma unroll
        for (int in = 0; in < 4; in++){
            int c0 = nBase + wn*32 + in*8 + (lane & 3)*2;
            float2 v0 = {acc[im][in][0], acc[im][in][1]};
            float2 v1 = {acc[im][in][2], acc[im][in][3]};
            *(float2*)&C[(size_t)r0*1024 + c0]       = v0;
            *(float2*)&C[(size_t)(r0+8)*1024 + c0]   = v1;
        }
    }
}

// =====================================================================
// xsplit + beta: one block per (b,l) row. Splits x into fp16 hi/lo and
// computes beta = sigmoid(x @ Wb) with the same reduction tree as the
// old conv kernel.
// =====================================================================
__global__ __launch_bounds__(256) void xsplit_kernel(const float* __restrict__ x,
                                                     __half* __restrict__ xh,
                                                     __half* __restrict__ xl,
                                                     const float* __restrict__ Wb)
{
    __shared__ float sbp[4][8];
    int row = blockIdx.x;            // b*4096 + l
    int t = threadIdx.x;
    int p0 = t * 4;
    size_t idx = (size_t)row * 1024 + p0;
    int warp = t >> 5, lane = t & 31;

    float4 v = *(const float4*)&x[idx];
    uint32_t h0,l0,h1,l1;
    split2h(v.x, v.y, h0, l0);
    split2h(v.z, v.w, h1, l1);
    uint2 hh = {h0, h1}, ll = {l0, l1};
    *(uint2*)&xh[idx] = hh;
    *(uint2*)&xl[idx] = ll;

    // beta partials
    float xa[4] = {v.x, v.y, v.z, v.w};
    float bp[4] = {0,0,0,0};
    #pragma unroll
    for (int ii=0;ii<4;ii++){
        float4 wb = *(const float4*)&Wb[(p0+ii)*4];
        bp[0] = fmaf(xa[ii], wb.x, bp[0]);
        bp[1] = fmaf(xa[ii], wb.y, bp[1]);
        bp[2] = fmaf(xa[ii], wb.z, bp[2]);
        bp[3] = fmaf(xa[ii], wb.w, bp[3]);
    }
    #pragma unroll
    for (int o=16;o;o>>=1){
        bp[0] += __shfl_xor_sync(0xffffffffu, bp[0], o);
        bp[1] += __shfl_xor_sync(0xffffffffu, bp[1], o);
        bp[2] += __shfl_xor_sync(0xffffffffu, bp[2], o);
        bp[3] += __shfl_xor_sync(0xffffffffu, bp[3], o);
    }
    if (lane == 0){
        sbp[0][warp] = bp[0]; sbp[1][warp] = bp[1];
        sbp[2][warp] = bp[2]; sbp[3][warp] = bp[3];
    }
    __syncthreads();
    if (t < 4){
        int b = row >> 12, l = row & 4095;
        float s = sbp[t][0]+sbp[t][1]+sbp[t][2]+sbp[t][3]
                 +sbp[t][4]+sbp[t][5]+sbp[t][6]+sbp[t][7];
        g_beta[((size_t)(b*4 + t))*4096 + l] = 1.f/(1.f + expf(-s));
    }
}

// merged weight transpose: 4 weights in one launch (grid.z = 4)
__global__ __launch_bounds__(256) void wsplit_kernel(
    const float* __restrict__ W0, const float* __restrict__ W1,
    const float* __restrict__ W2, const float* __restrict__ W3,
    __half* __restrict__ T0, __half* __restrict__ T1,
    __half* __restrict__ T2, __half* __restrict__ T3)
{
    __shared__ float tile[32][33];
    int z = blockIdx.z;
    const float* W = (z==0)?W0:(z==1)?W1:(z==2)?W2:W3;
    __half* Th     = (z==0)?T0:(z==1)?T1:(z==2)?T2:T3;
    int k0 = blockIdx.y * 32, n0 = blockIdx.x * 32;
    int tx = threadIdx.x & 31, ty = threadIdx.x >> 5;
    #pragma unroll
    for (int i = 0; i < 32; i += 8)
        tile[ty+i][tx] = W[(size_t)(k0+ty+i)*1024 + n0+tx];
    __syncthreads();
    #pragma unroll
    for (int i = 0; i < 32; i += 8){
        float v = tile[tx][ty+i];
        Th[(size_t)(n0+ty+i)*1024 + k0+tx] = __float2half_rn(v);
    }
}

// =====================================================================
// Fused conv(KW=4)+SiLU+L2norm (beta moved to xsplit). Strip of TLc
// l-positions; ping-pong q/k reductions, 1 barrier per iteration.
// =====================================================================
#define TLc 16
__global__ __launch_bounds__(256, 2) void conv_kernel(
    const float* __restrict__ cq, const float* __restrict__ ck,
    const float* __restrict__ cv)
{
    __shared__ float sq[2][8], sk[2][8];
    int strip = blockIdx.x;
    int row0 = strip * TLc;
    int b = row0 >> 12;
    int l0 = row0 & 4095;
    int t = threadIdx.x;
    int p0 = t * 4;
    int h = p0 >> 8;
    int d0 = p0 & 255;
    int warp = t >> 5, lane = t & 31;

    float wq[16], wk[16], wv[16];
    #pragma unroll
    for (int i=0;i<4;i++){
        *(float4*)&wq[i*4]  = *(const float4*)&cq[(p0+i)*4];
        *(float4*)&wk[i*4]  = *(const float4*)&ck[(p0+i)*4];
        *(float4*)&wv[i*4]  = *(const float4*)&cv[(p0+i)*4];
    }

    float hq[3][4], hk[3][4], hv[3][4];
    #pragma unroll
    for (int j=0;j<3;j++){
        int lj = l0 - 3 + j;
        if (lj >= 0){
            size_t base = ((size_t)(b*4096 + lj))*1024 + p0;
            *(float4*)hq[j] = ld4h(&g_qlinh[base]);
            *(float4*)hk[j] = ld4h(&g_klinh[base]);
            *(float4*)hv[j] = ld4h(&g_vlinh[base]);
        } else {
            #pragma unroll
            for (int ii=0;ii<4;ii++){ hq[j][ii]=0.f; hk[j][ii]=0.f; hv[j][ii]=0.f; }
        }
    }

    #pragma unroll 1
    for (int it = 0; it < TLc; ++it){
        int pp = it & 1;
        int l = l0 + it;
        size_t base = ((size_t)(b*4096 + l))*1024 + p0;
        float cqv[4], ckv[4], cvv[4];
        *(float4*)cqv = ld4h(&g_qlinh[base]);
        *(float4*)ckv = ld4h(&g_klinh[base]);
        *(float4*)cvv = ld4h(&g_vlinh[base]);

        float q4[4], k4[4], v4[4];
        #pragma unroll
        for (int ii=0;ii<4;ii++){
            q4[ii] = fmaf(wq[ii*4+0],hq[0][ii], fmaf(wq[ii*4+1],hq[1][ii],
                     fmaf(wq[ii*4+2],hq[2][ii], wq[ii*4+3]*cqv[ii])));
            k4[ii] = fmaf(wk[ii*4+0],hk[0][ii], fmaf(wk[ii*4+1],hk[1][ii],
                     fmaf(wk[ii*4+2],hk[2][ii], wk[ii*4+3]*ckv[ii])));
            v4[ii] = fmaf(wv[ii*4+0],hv[0][ii], fmaf(wv[ii*4+1],hv[1][ii],
                     fmaf(wv[ii*4+2],hv[2][ii], wv[ii*4+3]*cvv[ii])));
        }
        #pragma unroll
        for (int ii=0;ii<4;ii++){
            hq[0][ii]=hq[1][ii]; hq[1][ii]=hq[2][ii]; hq[2][ii]=cqv[ii];
            hk[0][ii]=hk[1][ii]; hk[1][ii]=hk[2][ii]; hk[2][ii]=ckv[ii];
            hv[0][ii]=hv[1][ii]; hv[1][ii]=hv[2][ii]; hv[2][ii]=cvv[ii];
        }
        #pragma unroll
        for (int ii=0;ii<4;ii++){
            q4[ii] = q4[ii] / (1.f + expf(-q4[ii]));
            k4[ii] = k4[ii] / (1.f + expf(-k4[ii]));
            v4[ii] = v4[ii] / (1.f + expf(-v4[ii]));
        }

        float qs = q4[0]*q4[0]+q4[1]*q4[1]+q4[2]*q4[2]+q4[3]*q4[3];
        float ks = k4[0]*k4[0]+k4[1]*k4[1]+k4[2]*k4[2]+k4[3]*k4[3];
        #pragma unroll
        for (int o=16;o;o>>=1){
            qs += __shfl_xor_sync(0xffffffffu, qs, o);
            ks += __shfl_xor_sync(0xffffffffu, ks, o);
        }
        if (lane == 0){
            sq[pp][warp] = qs; sk[pp][warp] = ks;
        }
        __syncthreads();
        float qsum = sq[pp][2*h] + sq[pp][2*h+1];
        float ksum = sk[pp][2*h] + sk[pp][2*h+1];
        float qi = rsqrtf(qsum) * 0.0625f;
        float ki = rsqrtf(ksum);
        size_t ob = (((size_t)(b*4 + h))*4096 + l)*256 + d0;
        uint32_t h0,l0b,h1,l1;
        split2h(q4[0]*qi, q4[1]*qi, h0, l0b);
        split2h(q4[2]*qi, q4[3]*qi, h1, l1);
        { uint2 hh = {h0,h1}, ll = {l0b,l1};
          *(uint2*)&g_Qbh[ob] = hh; *(uint2*)&g_Qbl[ob] = ll; }
        split2h(k4[0]*ki, k4[1]*ki, h0, l0b);
        split2h(k4[2]*ki, k4[3]*ki, h1, l1);
        { uint2 hh = {h0,h1}, ll = {l0b,l1};
          *(uint2*)&g_Kbh[ob] = hh; *(uint2*)&g_Kbl[ob] = ll; }
        { uint2 hh = {pack2h(v4[0], v4[1]), pack2h(v4[2], v4[3])};
          *(uint2*)&g_Vbh[ob] = hh; }
        // no trailing barrier: ping-pong buffers
    }
}

// =====================================================================
// Tensorized chunk precompute, fp16 2-pass (A keeps lo, B hi-only).
// =====================================================================
#define PP_KQH 0
#define PP_KQL 67584
#define PP_VH  135168
#define PP_BYTES 202752
#define PP_ASH 33792
#define PP_TSH 50688
#define PP_TBH 101376
#define PP_TBL 110592
#define PP_SCR 119808

__global__ __launch_bounds__(256) void prep_kernel()
{
    extern __shared__ char smc[];
    uint32_t sb = smem_u32(smc);
    __shared__ float bsh[64];
    float* Ash = (float*)(smc + PP_ASH);
    float* Tsh = (float*)(smc + PP_TSH);
    float* SCR = (float*)(smc + PP_SCR);

    int ch = blockIdx.x, bh = blockIdx.y;
    int tid = threadIdx.x, lane = tid & 31, wid = tid >> 5;
    size_t rowbase = (size_t)bh*Ln + ch*Cn;
    size_t gbase = ((size_t)(bh*NCn + ch))*4096;

    #pragma unroll
    for (int i=0;i<16;i++){
        int flat = tid + i*256;
        int r = flat >> 5, cc = flat & 31;
        const __half* ph = (r < 64) ? g_Kbh : g_Qbh;
        const __half* pl = (r < 64) ? g_Kbl : g_Qbl;
        size_t src = (rowbase + (r & 63))*256 + cc*8;
        cp_async16(sb + PP_KQH + (uint32_t)(r*528 + cc*16), ph + src);
        cp_async16(sb + PP_KQL + (uint32_t)(r*528 + cc*16), pl + src);
    }
    #pragma unroll
    for (int i=0;i<8;i++){
        int flat = tid + i*256;
        int r = flat >> 5, cc = flat & 31;
        size_t src = (rowbase + r)*256 + cc*8;
        cp_async16(sb + PP_VH + (uint32_t)(r*528 + cc*16), g_Vbh + src);
    }
    if (tid < 64) bsh[tid] = g_beta[(size_t)bh*Ln + ch*Cn + tid];
    cp_commit(); cp_wait<0>(); __syncthreads();

    float acc[4][2][4];
    #pragma unroll
    for (int nb=0;nb<4;nb++)
        #pragma unroll
        for (int f=0;f<2;f++)
            #pragma unroll
            for (int q=0;q<4;q++) acc[nb][f][q] = 0.f;

    uint32_t aOffH = PP_KQH + (uint32_t)((wid*16 + (lane & 15))*528 + ((lane >> 4) << 4));
    uint32_t aOffL = aOffH + (PP_KQL - PP_KQH);
    uint32_t bLane = (uint32_t)(((lane & 7) + ((lane >> 4) << 3))*528 + (((lane >> 3) & 1) << 4));

    for (int ks = 0; ks < 16; ++ks){
        uint32_t off = (uint32_t)(ks*32);
        uint32_t ah[4], al[4];
        ldsm_x4(ah, sb + aOffH + off);
        ldsm_x4(al, sb + aOffL + off);
        #pragma unroll
        for (int nb = 0; nb < 4; nb++){
            uint32_t ba = sb + PP_KQH + bLane + (uint32_t)(nb*16*528) + off;
            uint32_t bhf[4];
            ldsm_x4(bhf, ba);
            mma16816_hf32(acc[nb][0], ah, bhf[0], bhf[1]);
            mma16816_hf32(acc[nb][0], al, bhf[0], bhf[1]);
            mma16816_hf32(acc[nb][1], ah, bhf[2], bhf[3]);
            mma16816_hf32(acc[nb][1], al, bhf[2], bhf[3]);
        }
    }
    __syncthreads();

    int r0 = wid*16 + (lane >> 2);
    if (wid < 4){
        #pragma unroll
        for (int nb = 0; nb < 4; nb++)
            #pragma unroll
            for (int f = 0; f < 2; f++){
                int c = nb*16 + f*8 + (lane & 3)*2;
                float vals[2][2] = {{acc[nb][f][0], acc[nb][f][1]},
                                    {acc[nb][f][2], acc[nb][f][3]}};
                #pragma unroll
                for (int hr = 0; hr < 2; hr++){
                    int rr = r0 + hr*8;
                    #pragma unroll
                    for (int jc = 0; jc < 2; jc++){
                        int cc = c + jc;
                        if (rr > cc)      Ash[rr*66 + cc] = bsh[rr]*vals[hr][jc];
                        else if (rr == cc) Ash[rr*66 + cc] = 1.f;
                    }
                }
            }
    } else {
        int gr0 = r0 - 64;
        #pragma unroll
        for (int nb = 0; nb < 4; nb++)
            #pragma unroll
            for (int f = 0; f < 2; f++){
                int c = nb*16 + f*8 + (lane & 3)*2;
                #pragma unroll
                for (int hr = 0; hr < 2; hr++){
                    int gr = gr0 + hr*8;
                    float m0 = (c   <= gr) ? acc[nb][f][hr*2+0] : 0.f;
                    float m1 = (c+1 <= gr) ? acc[nb][f][hr*2+1] : 0.f;
                    uint32_t ho, lo;
                    split2h(m0, m1, ho, lo);
                    *(uint32_t*)&g_Gbh[gbase + gr*64 + c] = ho;
                    *(uint32_t*)&g_Gbl[gbase + gr*64 + c] = lo;
                }
            }
    }
    for (int f = tid; f < 64*66; f += 256) Tsh[f] = 0.f;
    __syncthreads();

    if (tid < 64){
        int Bb = tid >> 4, jj = tid & 15, base = Bb*16;
        Tsh[(base+jj)*66 + base+jj] = 1.f;
        for (int i = jj+1; i < 16; i++){
            float s = 0.f;
            for (int m = jj; m < i; m++)
                s = fmaf(Ash[(base+i)*66 + base+m], Tsh[(base+m)*66 + base+jj], s);
            Tsh[(base+i)*66 + base+jj] = -s;
        }
    }
    __syncthreads();

    {
        int ii = tid >> 4, jj = tid & 15;
        for (int I = 1; I < 4; I++){
            for (int J = 0; J < I; J++){
                float s = 0.f;
                for (int K = J; K < I; K++){
                    #pragma unroll
                    for (int m = 0; m < 16; m++)
                        s = fmaf(Ash[(I*16+ii)*66 + K*16+m], Tsh[(K*16+m)*66 + J*16+jj], s);
                }
                SCR[(J*16+ii)*17 + jj] = s;
            }
            __syncthreads();
            for (int J = 0; J < I; J++){
                float v = 0.f;
                #pragma unroll
                for (int m = 0; m < 16; m++)
                    v = fmaf(Tsh[(I*16+ii)*66 + I*16+m], SCR[(J*16+m)*17 + jj], v);
                Tsh[(I*16+ii)*66 + J*16+jj] = -v;
            }
            __syncthreads();
        }
    }

    {
        int r = tid >> 2;
        int cb = (tid & 3)*16;
        #pragma unroll
        for (int p = 0; p < 8; p++){
            int c = cb + p*2;
            float v0 = Tsh[r*66 + c]   * bsh[c];
            float v1 = Tsh[r*66 + c+1] * bsh[c+1];
            uint32_t ho, lo;
            split2h(v0, v1, ho, lo);
            *(uint32_t*)(smc + PP_TBH + r*144 + c*2) = ho;
            *(uint32_t*)(smc + PP_TBL + r*144 + c*2) = lo;
        }
    }
    __syncthreads();

    {
        int wm = wid & 3, sel = wid >> 2;
        uint32_t bBase = sel ? PP_VH : PP_KQH;
        uint32_t aOff2 = PP_TBH + (uint32_t)((wm*16 + (lane & 15))*144 + ((lane >> 4) << 4));
        uint32_t bl2 = (uint32_t)(((((lane >> 3) & 1)*8) + (lane & 7))*528 + ((lane >> 4) << 4));

        for (int nc = 0; nc < 4; nc++){
            float a2[8][4];
            #pragma unroll
            for (int i=0;i<8;i++)
                #pragma unroll
                for (int q=0;q<4;q++) a2[i][q] = 0.f;
            #pragma unroll
            for (int ks = 0; ks < 4; ks++){
                uint32_t ath[4], atl[4];
                ldsm_x4(ath, sb + aOff2 + (uint32_t)(ks*32));
                ldsm_x4(atl, sb + aOff2 + (uint32_t)(PP_TBL - PP_TBH) + (uint32_t)(ks*32));
                #pragma unroll
                for (int nf = 0; nf < 4; nf++){
                    uint32_t ba = sb + bBase + bl2 + (uint32_t)(ks*16*528 + (nc*64 + nf*16)*2);
                    uint32_t kh[4];
                    ldsm_x4_t(kh, ba);
                    mma16816_hf32(a2[nf*2],   ath, kh[0], kh[1]);
                    mma16816_hf32(a2[nf*2],   atl, kh[0], kh[1]);
                    mma16816_hf32(a2[nf*2+1], ath, kh[2], kh[3]);
                    mma16816_hf32(a2[nf*2+1], atl, kh[2], kh[3]);
                }
            }
            int rr = wm*16 + (lane >> 2);
            #pragma unroll
            for (int nf = 0; nf < 4; nf++)
                #pragma unroll
                for (int hf = 0; hf < 2; hf++){
                    int d = nc*64 + nf*16 + hf*8 + (lane & 3)*2;
                    int idx = nf*2 + hf;
                    if (sel == 0){
                        uint32_t ho, lo;
                        split2h(a2[idx][0], a2[idx][1], ho, lo);
                        *(uint32_t*)&g_Wbh[(rowbase + rr)*256 + d] = ho;
                        *(uint32_t*)&g_Wbl[(rowbase + rr)*256 + d] = lo;
                        split2h(a2[idx][2], a2[idx][3], ho, lo);
                        *(uint32_t*)&g_Wbh[(rowbase + rr + 8)*256 + d] = ho;
                        *(uint32_t*)&g_Wbl[(rowbase + rr + 8)*256 + d] = lo;
                    } else {
                        float2 v0 = {a2[idx][0], a2[idx][1]};
                        float2 v1 = {a2[idx][2], a2[idx][3]};
                        *(float2*)&g_U[(rowbase + rr)*256 + d]     = v0;
                        *(float2*)&g_U[(rowbase + rr + 8)*256 + d] = v1;
                    }
                }
        }
    }
}

// =====================================================================
// Sequential chunk scan, fp16 2-pass everywhere.
// =====================================================================
#define OFF_S   0
#define OFF_SH  33280
#define OFF_WQH 67072
#define OFF_WQL 134656
#define OFF_KBH OFF_WQH
#define OFF_GBH 202240
#define OFF_GBL 211456
#define OFF_MTH 220672
#define OFF_MTL 225280
#define SCAN_SMEM_BYTES 229888
#define SPITCH 528
#define MPITCH 144

__device__ __forceinline__ void store_mt(char* smc, int d, int c, float m){
    __half h = __float2half_rn(m);
    float lo = m - __half2float(h);
    *(__half*)(smc + OFF_MTH + d*MPITCH + c*2) = h;
    *(__half*)(smc + OFF_MTL + d*MPITCH + c*2) = __float2half_rn(lo);
}

__global__ __launch_bounds__(256) void scan_kernel(float* __restrict__ Sout)
{
    extern __shared__ char smc[];
    uint32_t sb = smem_u32(smc);
    float* Ssh = (float*)(smc + OFF_S);

    int bx = blockIdx.x;
    int bh = bx >> 3;
    int dt = bx & 7;
    int d0 = dt * 32;
    int tid = threadIdx.x;
    int lane = tid & 31, wid = tid >> 5;

    for (int f = tid; f < 32*260; f += 256) Ssh[f] = 0.f;
    __syncthreads();

    uint32_t aOffH = OFF_WQH + (uint32_t)(wid*16 + (lane & 15))*SPITCH + ((lane >> 4) << 4);
    uint32_t aOffL = aOffH + (OFF_WQL - OFF_WQH);
    uint32_t bRowOff = (uint32_t)((lane & 7) + ((lane >> 4) << 3))*SPITCH + (((lane >> 3) & 1) << 4);

    for (int ch = 0; ch < NCn; ++ch){
        size_t rowbase = (size_t)bh*Ln + ch*Cn;
        size_t gbaseE = ((size_t)(bh*NCn + ch))*(Cn*Cn);

        #pragma unroll
        for (int i = 0; i < 16; i++){
            int flat = tid + i*256;
            int r = flat >> 5;
            int cch = flat & 31;
            size_t src = (r < 64) ? (rowbase + r)*256 + cch*8
                                  : (rowbase + r - 64)*256 + cch*8;
            const __half* ph = (r < 64) ? g_Wbh : g_Qbh;
            const __half* pl = (r < 64) ? g_Wbl : g_Qbl;
            cp_async16(sb + OFF_WQH + (uint32_t)(r*SPITCH + cch*16), ph + src);
            cp_async16(sb + OFF_WQL + (uint32_t)(r*SPITCH + cch*16), pl + src);
        }
        #pragma unroll
        for (int i = 0; i < 4; i++){
            int flat = tid + i*256;
            int half2i = flat >> 9;
            int idx = flat & 511;
            int r = idx >> 3, cch = idx & 7;
            const __half* pg = half2i ? g_Gbl : g_Gbh;
            uint32_t dstoff = half2i ? OFF_GBL : OFF_GBH;
            cp_async16(sb + dstoff + (uint32_t)(r*MPITCH + cch*16), pg + gbaseE + r*64 + cch*8);
        }
        cp_commit();

        {
            int r = tid >> 3;
            int cc = (tid & 7) * 32;
            #pragma unroll
            for (int j = 0; j < 8; j++){
                float4 v = *(float4*)&Ssh[r*260 + cc + j*4];
                uint2 hh = {pack2h(v.x, v.y), pack2h(v.z, v.w)};
                *(uint2*)(smc + OFF_SH + r*SPITCH + cc*2 + j*8) = hh;
            }
        }
        cp_wait<0>();
        __syncthreads();

        float acc[4][4];
        #pragma unroll
        for (int i=0;i<4;i++)
            #pragma unroll
            for (int q=0;q<4;q++) acc[i][q] = 0.f;

        for (int ks = 0; ks < 16; ++ks){
            uint32_t off = (uint32_t)(ks*32);
            uint32_t ah[4], al[4], b0h[4], b1h[4];
            ldsm_x4(ah, sb + aOffH + off);
            ldsm_x4(al, sb + aOffL + off);
            ldsm_x4(b0h, sb + OFF_SH + bRowOff + off);
            ldsm_x4(b1h, sb + OFF_SH + 16*SPITCH + bRowOff + off);
            mma16816_hf32(acc[0], ah, b0h[0], b0h[1]);
            mma16816_hf32(acc[0], al, b0h[0], b0h[1]);
            mma16816_hf32(acc[1], ah, b0h[2], b0h[3]);
            mma16816_hf32(acc[1], al, b0h[2], b0h[3]);
            mma16816_hf32(acc[2], ah, b1h[0], b1h[1]);
            mma16816_hf32(acc[2], al, b1h[0], b1h[1]);
            mma16816_hf32(acc[3], ah, b1h[2], b1h[3]);
            mma16816_hf32(acc[3], al, b1h[2], b1h[3]);
        }

        int crow = wid*16 + (lane >> 2);
        if (wid < 4){
            #pragma unroll
            for (int in = 0; in < 4; in++){
                int d = in*8 + (lane & 3)*2;
                float2 u0 = *(const float2*)&g_U[(rowbase + crow)*256 + d0 + d];
                float2 u1 = *(const float2*)&g_U[(rowbase + crow + 8)*256 + d0 + d];
                store_mt(smc, d,   crow,     u0.x - acc[in][0]);
                store_mt(smc, d+1, crow,     u0.y - acc[in][1]);
                store_mt(smc, d,   crow + 8, u1.x - acc[in][2]);
                store_mt(smc, d+1, crow + 8, u1.y - acc[in][3]);
            }
        } else {
            int c = crow - 64;
            #pragma unroll
            for (int in = 0; in < 4; in++){
                int d = in*8 + (lane & 3)*2;
                float2 v0 = {acc[in][0], acc[in][1]};
                float2 v1 = {acc[in][2], acc[in][3]};
                *(float2*)&g_o[(rowbase + c)*256 + d0 + d]     = v0;
                *(float2*)&g_o[(rowbase + c + 8)*256 + d0 + d] = v1;
            }
        }
        __syncthreads();

        #pragma unroll
        for (int i = 0; i < 8; i++){
            int flat = tid + i*256;
            int r = flat >> 5, cch = flat & 31;
            cp_async16(sb + OFF_KBH + (uint32_t)(r*SPITCH + cch*16),
                       g_Kbh + (rowbase + r)*256 + cch*8);
        }
        cp_commit();

        {
            int wm2 = wid >> 1, wn2 = wid & 1;
            uint32_t aOff2 = sb + OFF_GBH + (uint32_t)((wm2*16 + (lane & 15))*MPITCH + ((lane >> 4) << 4));
            uint32_t bOff2 = sb + OFF_MTH + (uint32_t)((wn2*16 + (lane & 7) + ((lane >> 4) << 3))*MPITCH + (((lane >> 3) & 1) << 4));
            float a2[2][4];
            #pragma unroll
            for (int f=0;f<2;f++)
                #pragma unroll
                for (int q=0;q<4;q++) a2[f][q] = 0.f;
            #pragma unroll
            for (int ks = 0; ks < 4; ++ks){
                uint32_t off = (uint32_t)(ks*32);
                uint32_t gah[4], gal[4], mbh[4];
                ldsm_x4(gah, aOff2 + off);
                ldsm_x4(gal, aOff2 + (OFF_GBL - OFF_GBH) + off);
                ldsm_x4(mbh, bOff2 + off);
                #pragma unroll
                for (int f = 0; f < 2; f++){
                    int j = f*2;
                    mma16816_hf32(a2[f], gah, mbh[j], mbh[j+1]);
                    mma16816_hf32(a2[f], gal, mbh[j], mbh[j+1]);
                }
            }
            int c = wm2*16 + (lane >> 2);
            #pragma unroll
            for (int f = 0; f < 2; f++){
                int d = wn2*16 + f*8 + (lane & 3)*2;
                float2 t0 = *(const float2*)&g_o[(rowbase + c)*256 + d0 + d];
                float2 t1 = *(const float2*)&g_o[(rowbase + c + 8)*256 + d0 + d];
                t0.x += a2[f][0]; t0.y += a2[f][1];
                t1.x += a2[f][2]; t1.y += a2[f][3];
                *(float2*)&g_o[(rowbase + c)*256 + d0 + d]     = t0;
                *(float2*)&g_o[(rowbase + c + 8)*256 + d0 + d] = t1;
            }
        }
        cp_wait<0>();
        __syncthreads();

        {
            int wm3 = wid >> 2, wn3 = wid & 3;
            uint32_t aOff3 = sb + OFF_MTH + (uint32_t)((wm3*16 + (lane & 15))*MPITCH + ((lane >> 4) << 4));
            uint32_t bLane = (uint32_t)((((lane >> 3) & 1)*8 + (lane & 7))*SPITCH + ((lane >> 4) << 4));
            float a3[8][4];
            #pragma unroll
            for (int i=0;i<8;i++)
                #pragma unroll
                for (int q=0;q<4;q++) a3[i][q] = 0.f;
            #pragma unroll
            for (int ks = 0; ks < 4; ++ks){
                uint32_t mtH[4], mtL[4];
                ldsm_x4(mtH, aOff3 + (uint32_t)(ks*32));
                ldsm_x4(mtL, aOff3 + (OFF_MTL - OFF_MTH) + (uint32_t)(ks*32));
                #pragma unroll
                for (int nf = 0; nf < 4; nf++){
                    int n0 = wn3*64 + nf*16;
                    uint32_t ba = sb + OFF_KBH + bLane + (uint32_t)(ks*16*SPITCH + n0*2);
                    uint32_t kh[4];
                    ldsm_x4_t(kh, ba);
                    mma16816_hf32(a3[nf*2],   mtH, kh[0], kh[1]);
                    mma16816_hf32(a3[nf*2],   mtL, kh[0], kh[1]);
                    mma16816_hf32(a3[nf*2+1], mtH, kh[2], kh[3]);
                    mma16816_hf32(a3[nf*2+1], mtL, kh[2], kh[3]);
                }
            }
            int d = wm3*16 + (lane >> 2);
            #pragma unroll
            for (int nf = 0; nf < 4; nf++){
                #pragma unroll
                for (int hf = 0; hf < 2; hf++){
                    int e = wn3*64 + nf*16 + hf*8 + (lane & 3)*2;
                    int idx = nf*2 + hf;
                    Ssh[d*260 + e]         += a3[idx][0];
                    Ssh[d*260 + e + 1]     += a3[idx][1];
                    Ssh[(d+8)*260 + e]     += a3[idx][2];
                    Ssh[(d+8)*260 + e + 1] += a3[idx][3];
                }
            }
        }
        __syncthreads();
    }

    if (Sout){
        for (int f = tid; f < 32*256; f += 256){
            int dr = f >> 8, e = f & 255;
            Sout[((size_t)bh*256 + d0 + dr)*256 + e] = Ssh[dr*260 + e];
        }
    }
}

// =====================================================================
// RMSNorm + regather to (b,l,p) as fp16 hi/lo split (for final GEMM).
// =====================================================================
__global__ __launch_bounds__(256) void rms_kernel(const float* __restrict__ rmsw)
{
    int tid = threadIdx.x;
    int w = tid >> 5, lane = tid & 31;
    size_t r = (size_t)blockIdx.x * 8 + w;
    int bh = (int)(r >> 12);
    int l  = (int)(r & 4095);
    int b = bh >> 2, h = bh & 3;
    const float* op = &g_o[r*256];
    float4 v0 = *(const float4*)&op[lane*4];
    float4 v1 = *(const float4*)&op[128 + lane*4];
    float ss = v0.x*v0.x+v0.y*v0.y+v0.z*v0.z+v0.w*v0.w
             + v1.x*v1.x+v1.y*v1.y+v1.z*v1.z+v1.w*v1.w;
    #pragma unroll
    for (int o=16;o;o>>=1) ss += __shfl_xor_sync(0xffffffffu, ss, o);
    float scale = rsqrtf(ss * (1.f/256.f) + 1e-5f);
    float4 w0 = *(const float4*)&rmsw[lane*4];
    float4 w1 = *(const float4*)&rmsw[128 + lane*4];
    float o0[4] = {v0.x*scale*w0.x, v0.y*scale*w0.y, v0.z*scale*w0.z, v0.w*scale*w0.w};
    float o1[4] = {v1.x*scale*w1.x, v1.y*scale*w1.y, v1.z*scale*w1.z, v1.w*scale*w1.w};
    size_t obase = ((size_t)(b*4096 + l))*1024 + h*256;
    uint32_t h0,l0,h1,l1;
    split2h(o0[0], o0[1], h0, l0);
    split2h(o0[2], o0[3], h1, l1);
    uint2 hh = {h0,h1}, ll = {l0,l1};
    *(uint2*)&g_onh[obase + lane*4] = hh;
    *(uint2*)&g_onl[obase + lane*4] = ll;
    split2h(o1[0], o1[1], h0, l0);
    split2h(o1[2], o1[3], h1, l1);
    uint2 hh2 = {h0,h1}, ll2 = {l0,l1};
    *(uint2*)&g_onh[obase + 128 + lane*4] = hh2;
    *(uint2*)&g_onl[obase + 128 + lane*4] = ll2;
}

// =====================================================================
extern "C" void kernel_launch(void* const* d_in, const int* in_sizes, int n_in,
                              void* d_out, int out_size)
{
    const float* x   = (const float*)d_in[0];
    const float* Wq  = (const float*)d_in[1];
    const float* Wk  = (const float*)d_in[2];
    const float* Wv  = (const float*)d_in[3];
    const float* Wb  = (const float*)d_in[4];
    const float* cq  = (const float*)d_in[5];
    const float* ck  = (const float*)d_in[6];
    const float* cv  = (const float*)d_in[7];
    const float* rw  = (const float*)d_in[8];
    const float* Wo  = (const float*)d_in[9];
    float* out = (float*)d_out;

    __half *qlin, *klin, *vlin;
    __half *xh, *xl, *onh, *onl, *wT;
    cudaGetSymbolAddress((void**)&qlin, g_qlinh);
    cudaGetSymbolAddress((void**)&klin, g_klinh);
    cudaGetSymbolAddress((void**)&vlin, g_vlinh);
    cudaGetSymbolAddress((void**)&xh,  g_xh);
    cudaGetSymbolAddress((void**)&xl,  g_xl);
    cudaGetSymbolAddress((void**)&onh, g_onh);
    cudaGetSymbolAddress((void**)&onl, g_onl);
    cudaGetSymbolAddress((void**)&wT,  g_wT);
    const size_t WSZ = 1024*1024;
    __half *wqh = wT;
    __half *wkh = wT + 2*WSZ;
    __half *wvh = wT + 4*WSZ;
    __half *woh = wT + 6*WSZ;

    cudaFuncSetAttribute(prep_kernel, cudaFuncAttributeMaxDynamicSharedMemorySize, PP_BYTES);
    cudaFuncSetAttribute(scan_kernel, cudaFuncAttributeMaxDynamicSharedMemorySize, SCAN_SMEM_BYTES);
    cudaFuncSetAttribute(gemm_qkv,    cudaFuncAttributeMaxDynamicSharedMemorySize, GEMM_SMEM);
    cudaFuncSetAttribute(gemm_out,    cudaFuncAttributeMaxDynamicSharedMemorySize, GEMM_SMEM);

    // merged weight transpose (one launch) + x split (now also computes beta)
    wsplit_kernel<<<dim3(32, 32, 4), 256>>>(Wq, Wk, Wv, Wo, wqh, wkh, wvh, woh);
    xsplit_kernel<<<ROWS, 256>>>(x, xh, xl, Wb);

    // merged QKV projection (fp16 out)
    gemm_qkv<<<dim3(8, 128, 3), 256, GEMM_SMEM>>>(xh, xl, wqh, wkh, wvh,
                                                  qlin, klin, vlin);

    conv_kernel<<<ROWS/TLc, 256>>>(cq, ck, cv);

    prep_kernel<<<dim3(NCn, BHn), 256, PP_BYTES>>>();

    float* Sout = (out_size >= ELEMS + BHn*Dn*Dn) ? (out + ELEMS) : nullptr;
    scan_kernel<<<128, 256, SCAN_SMEM_BYTES>>>(Sout);

    rms_kernel<<<(BHn*Ln)/8, 256>>>(rw);

    gemm_out<<<dim3(8, 128), 256, GEMM_SMEM>>>(onh, onl, woh, out);
}

// round 16
// speedup vs baseline: 1.0087x; 1.0087x over previous
#include <cuda_runtime.h>
#include <cuda_bf16.h>
#include <cuda_fp16.h>
#include <math.h>
#include <stdint.h>

// ---------------- problem constants ----------------
#define Bn   4
#define Ln   4096
#define Hn   4
#define Dn   256
#define Pn   1024
#define Cn   64
#define NCn  64
#define BHn  16
#define ROWS (Bn*Ln)            // 16384
#define ELEMS (ROWS*Pn)         // 16777216

// ---------------- device scratch (static, no runtime alloc) ----------------
__device__ float g_U[ELEMS];     // U = T' @ V   (b,h,l,d)
__device__ float g_beta[BHn*Ln];
__device__ float g_o[ELEMS];     // scan output (b,h,l,d)

// fp16 projection outputs (written directly by QKV GEMM)
__device__ __half g_qlinh[ELEMS];
__device__ __half g_klinh[ELEMS];
__device__ __half g_vlinh[ELEMS];

// fp16 split operands for the big GEMMs
__device__ __half g_xh[ELEMS];
__device__ __half g_xl[ELEMS];
__device__ __half g_onh[ELEMS];
__device__ __half g_onl[ELEMS];
__device__ __half g_wT[8][1024*1024];

// fp16 split operands for scan/prep tensor-core work
__device__ __half g_Wbh[ELEMS];
__device__ __half g_Wbl[ELEMS];
__device__ __half g_Qbh[ELEMS];
__device__ __half g_Qbl[ELEMS];
__device__ __half g_Kbh[ELEMS];
__device__ __half g_Kbl[ELEMS];
__device__ __half g_Vbh[ELEMS];
__device__ __half g_Gbh[BHn*NCn*Cn*Cn];
__device__ __half g_Gbl[BHn*NCn*Cn*Cn];

// =====================================================================
// helpers
// =====================================================================
__device__ __forceinline__ uint32_t smem_u32(const void* p){
    uint32_t a;
    asm("{ .reg .u64 t; cvta.to.shared.u64 t, %1; cvt.u32.u64 %0, t; }" : "=r"(a) : "l"(p));
    return a;
}
__device__ __forceinline__ void cp_async16(uint32_t dst, const void* src){
    asm volatile("cp.async.cg.shared.global [%0], [%1], 16;" :: "r"(dst), "l"(src) : "memory");
}
__device__ __forceinline__ void cp_commit(){ asm volatile("cp.async.commit_group;" ::: "memory"); }
template<int N> __device__ __forceinline__ void cp_wait(){ asm volatile("cp.async.wait_group %0;" :: "n"(N) : "memory"); }

__device__ __forceinline__ void ldsm_x4(uint32_t* r, uint32_t addr){
    asm volatile("ldmatrix.sync.aligned.m8n8.x4.shared.b16 {%0,%1,%2,%3}, [%4];"
        : "=r"(r[0]), "=r"(r[1]), "=r"(r[2]), "=r"(r[3]) : "r"(addr));
}
__device__ __forceinline__ void ldsm_x4_t(uint32_t* r, uint32_t addr){
    asm volatile("ldmatrix.sync.aligned.m8n8.x4.trans.shared.b16 {%0,%1,%2,%3}, [%4];"
        : "=r"(r[0]), "=r"(r[1]), "=r"(r[2]), "=r"(r[3]) : "r"(addr));
}
// fp16 mma, fp32 acc
__device__ __forceinline__ void mma16816_hf32(float* c, const uint32_t* a, uint32_t b0, uint32_t b1){
    asm volatile(
        "mma.sync.aligned.m16n8k16.row.col.f32.f16.f16.f32 "
        "{%0,%1,%2,%3}, {%4,%5,%6,%7}, {%8,%9}, {%0,%1,%2,%3};"
        : "+f"(c[0]), "+f"(c[1]), "+f"(c[2]), "+f"(c[3])
        : "r"(a[0]), "r"(a[1]), "r"(a[2]), "r"(a[3]), "r"(b0), "r"(b1));
}

__device__ __forceinline__ void split2h(float a, float b, uint32_t& ho, uint32_t& lo){
    __half ha = __float2half_rn(a), hb = __float2half_rn(b);
    float la = a - __half2float(ha);
    float lb = b - __half2float(hb);
    __half2 hv; hv.x = ha; hv.y = hb;
    __half2 lv; lv.x = __float2half_rn(la); lv.y = __float2half_rn(lb);
    ho = *(uint32_t*)&hv; lo = *(uint32_t*)&lv;
}
__device__ __forceinline__ uint32_t pack2h(float a, float b){
    __half2 hv; hv.x = __float2half_rn(a); hv.y = __float2half_rn(b);
    return *(uint32_t*)&hv;
}
__device__ __forceinline__ float4 ld4h(const __half* p){
    uint2 t = *(const uint2*)p;
    __half2 a = *(__half2*)&t.x, b = *(__half2*)&t.y;
    float2 fa = __half22float2(a), fb = __half22float2(b);
    float4 r; r.x = fa.x; r.y = fa.y; r.z = fb.x; r.w = fb.y;
    return r;
}

// =====================================================================
// fp16 2-pass GEMM mainloop (shared)
// =====================================================================
#define NKT2 32
#define P2   80
#define OPB2 (128*P2)
#define STG2 (3*OPB2)
#define GEMM_SMEM (2*STG2 + 128)

__device__ __forceinline__ void g_load_stage2(
    uint32_t sbase, int s, int kt,
    const __half* __restrict__ Ah, const __half* __restrict__ Al,
    const __half* __restrict__ Bh,
    int mBase, int nBase, int tid)
{
    uint32_t sb = sbase + (uint32_t)s * STG2;
    int kofs = kt * 32;
    #pragma unroll
    for (int i = 0; i < 6; i++){
        int flat = tid + i*256;
        int op   = flat >> 9;
        int idx  = flat & 511;
        int row  = idx >> 2;
        int ch   = idx & 3;
        uint32_t d = sb + (uint32_t)(op*OPB2 + row*P2 + ch*16);
        const __half* src;
        size_t g;
        if (op == 0){ src = Ah; g = (size_t)(mBase + row)*1024 + kofs + ch*8; }
        else if (op == 1){ src = Al; g = (size_t)(mBase + row)*1024 + kofs + ch*8; }
        else { src = Bh; g = (size_t)(nBase + row)*1024 + kofs + ch*8; }
        cp_async16(d, src + g);
    }
}

__device__ __forceinline__ void gemm_mainloop(
    uint32_t sbase,
    const __half* __restrict__ Ah, const __half* __restrict__ Al,
    const __half* __restrict__ Bh,
    int mBase, int nBase, int tid, int wid, int lane,
    float acc[4][4][4])
{
    int wm = wid >> 2;
    int wn = wid & 3;
    #pragma unroll
    for (int i=0;i<4;i++)
        #pragma unroll
        for (int j=0;j<4;j++)
            #pragma unroll
            for (int q=0;q<4;q++) acc[i][j][q] = 0.f;

    uint32_t aOff = (uint32_t)((wm*64 + (lane & 15))*P2 + ((lane >> 4) << 4));
    uint32_t bOff = (uint32_t)(2*OPB2 + (wn*32 + (lane & 7) + ((lane >> 4) << 3))*P2
                               + (((lane >> 3) & 1) << 4));

    g_load_stage2(sbase, 0, 0, Ah, Al, Bh, mBase, nBase, tid); cp_commit();

    for (int kt = 0; kt < NKT2; ++kt){
        if (kt + 1 < NKT2)
            g_load_stage2(sbase, (kt+1)&1, kt+1, Ah, Al, Bh, mBase, nBase, tid);
        cp_commit();
        cp_wait<1>();
        __syncthreads();

        uint32_t sb = sbase + (uint32_t)(kt & 1) * STG2;
        #pragma unroll
        for (int ks = 0; ks < 2; ++ks){
            uint32_t bb = sb + bOff + (uint32_t)(ks*32);
            uint32_t bh0[4], bh1[4];
            ldsm_x4(bh0, bb);
            ldsm_x4(bh1, bb + 16*P2);
            #pragma unroll
            for (int im = 0; im < 4; im++){
                uint32_t aa = sb + aOff + (uint32_t)(im*16*P2 + ks*32);
                uint32_t ah[4], al[4];
                ldsm_x4(ah, aa);
                ldsm_x4(al, aa + OPB2);
                #pragma unroll
                for (int in = 0; in < 4; in++){
                    const uint32_t* bhp = (in < 2) ? bh0 : bh1;
                    int j = (in & 1)*2;
                    mma16816_hf32(acc[im][in], ah, bhp[j], bhp[j+1]);
                    mma16816_hf32(acc[im][in], al, bhp[j], bhp[j+1]);
                }
            }
        }
        __syncthreads();
    }
}

// QKV triple GEMM: grid (8, 128, 3); fp16 output
__global__ __launch_bounds__(256, 2) void gemm_qkv(
    const __half* __restrict__ Ah, const __half* __restrict__ Al,
    const __half* __restrict__ B0, const __half* __restrict__ B1,
    const __half* __restrict__ B2,
    __half* __restrict__ C0, __half* __restrict__ C1, __half* __restrict__ C2)
{
    extern __shared__ char dsm[];
    uint32_t sbase = (smem_u32(dsm) + 127u) & ~127u;
    int tid = threadIdx.x, wid = tid >> 5, lane = tid & 31;
    int mBase = blockIdx.y * 128;
    int nBase = blockIdx.x * 128;
    int z = blockIdx.z;
    const __half* Bh = (z == 0) ? B0 : (z == 1) ? B1 : B2;
    __half* C = (z == 0) ? C0 : (z == 1) ? C1 : C2;

    float acc[4][4][4];
    gemm_mainloop(sbase, Ah, Al, Bh, mBase, nBase, tid, wid, lane, acc);

    int wm = wid >> 2, wn = wid & 3;
    #pragma unroll
    for (int im = 0; im < 4; im++){
        int r0 = mBase + wm*64 + im*16 + (lane >> 2);
        #pragma unroll
        for (int in = 0; in < 4; in++){
            int c0 = nBase + wn*32 + in*8 + (lane & 3)*2;
            *(uint32_t*)&C[(size_t)r0*1024 + c0]     = pack2h(acc[im][in][0], acc[im][in][1]);
            *(uint32_t*)&C[(size_t)(r0+8)*1024 + c0] = pack2h(acc[im][in][2], acc[im][in][3]);
        }
    }
}

// Wo GEMM: fp32 output
__global__ __launch_bounds__(256, 2) void gemm_out(
    const __half* __restrict__ Ah, const __half* __restrict__ Al,
    const __half* __restrict__ Bh,
    float* __restrict__ C)
{
    extern __shared__ char dsm[];
    uint32_t sbase = (smem_u32(dsm) + 127u) & ~127u;
    int tid = threadIdx.x, wid = tid >> 5, lane = tid & 31;
    int mBase = blockIdx.y * 128;
    int nBase = blockIdx.x * 128;

    float acc[4][4][4];
    gemm_mainloop(sbase, Ah, Al, Bh, mBase, nBase, tid, wid, lane, acc);

    int wm = wid >> 2, wn = wid & 3;
    #pragma unroll
    for (int im = 0; im < 4; im++){
        int r0 = mBase + wm*64 + im*16 + (lane >> 2);
        #pragma unroll
        for (int in = 0; in < 4; in++){
            int c0 = nBase + wn*32 + in*8 + (lane & 3)*2;
            float2 v0 = {acc[im][in][0], acc[im][in][1]};
            float2 v1 = {acc[im][in][2], acc[im][in][3]};
            *(float2*)&C[(size_t)r0*1024 + c0]       = v0;
            *(float2*)&C[(size_t)(r0+8)*1024 + c0]   = v1;
        }
    }
}

// =====================================================================
// xsplit + beta: one block per (b,l) row.
// =====================================================================
__global__ __launch_bounds__(256) void xsplit_kernel(const float* __restrict__ x,
                                                     __half* __restrict__ xh,
                                                     __half* __restrict__ xl,
                                                     const float* __restrict__ Wb)
{
    __shared__ float sbp[4][8];
    int row = blockIdx.x;            // b*4096 + l
    int t = threadIdx.x;
    int p0 = t * 4;
    size_t idx = (size_t)row * 1024 + p0;
    int warp = t >> 5, lane = t & 31;

    float4 v = *(const float4*)&x[idx];
    uint32_t h0,l0,h1,l1;
    split2h(v.x, v.y, h0, l0);
    split2h(v.z, v.w, h1, l1);
    uint2 hh = {h0, h1}, ll = {l0, l1};
    *(uint2*)&xh[idx] = hh;
    *(uint2*)&xl[idx] = ll;

    float xa[4] = {v.x, v.y, v.z, v.w};
    float bp[4] = {0,0,0,0};
    #pragma unroll
    for (int ii=0;ii<4;ii++){
        float4 wb = *(const float4*)&Wb[(p0+ii)*4];
        bp[0] = fmaf(xa[ii], wb.x, bp[0]);
        bp[1] = fmaf(xa[ii], wb.y, bp[1]);
        bp[2] = fmaf(xa[ii], wb.z, bp[2]);
        bp[3] = fmaf(xa[ii], wb.w, bp[3]);
    }
    #pragma unroll
    for (int o=16;o;o>>=1){
        bp[0] += __shfl_xor_sync(0xffffffffu, bp[0], o);
        bp[1] += __shfl_xor_sync(0xffffffffu, bp[1], o);
        bp[2] += __shfl_xor_sync(0xffffffffu, bp[2], o);
        bp[3] += __shfl_xor_sync(0xffffffffu, bp[3], o);
    }
    if (lane == 0){
        sbp[0][warp] = bp[0]; sbp[1][warp] = bp[1];
        sbp[2][warp] = bp[2]; sbp[3][warp] = bp[3];
    }
    __syncthreads();
    if (t < 4){
        int b = row >> 12, l = row & 4095;
        float s = sbp[t][0]+sbp[t][1]+sbp[t][2]+sbp[t][3]
                 +sbp[t][4]+sbp[t][5]+sbp[t][6]+sbp[t][7];
        g_beta[((size_t)(b*4 + t))*4096 + l] = 1.f/(1.f + expf(-s));
    }
}

// merged weight transpose: 4 weights in one launch (grid.z = 4)
__global__ __launch_bounds__(256) void wsplit_kernel(
    const float* __restrict__ W0, const float* __restrict__ W1,
    const float* __restrict__ W2, const float* __restrict__ W3,
    __half* __restrict__ T0, __half* __restrict__ T1,
    __half* __restrict__ T2, __half* __restrict__ T3)
{
    __shared__ float tile[32][33];
    int z = blockIdx.z;
    const float* W = (z==0)?W0:(z==1)?W1:(z==2)?W2:W3;
    __half* Th     = (z==0)?T0:(z==1)?T1:(z==2)?T2:T3;
    int k0 = blockIdx.y * 32, n0 = blockIdx.x * 32;
    int tx = threadIdx.x & 31, ty = threadIdx.x >> 5;
    #pragma unroll
    for (int i = 0; i < 32; i += 8)
        tile[ty+i][tx] = W[(size_t)(k0+ty+i)*1024 + n0+tx];
    __syncthreads();
    #pragma unroll
    for (int i = 0; i < 32; i += 8){
        float v = tile[tx][ty+i];
        Th[(size_t)(n0+ty+i)*1024 + k0+tx] = __float2half_rn(v);
    }
}

// =====================================================================
// Fused conv(KW=4)+SiLU+L2norm. History re-loaded from L1 (no register
// history) -> lower register pressure -> 3 CTAs/SM. Bitwise-identical
// arithmetic to round-15 conv.
// =====================================================================
#define TLc 16
__global__ __launch_bounds__(256, 3) void conv_kernel(
    const float* __restrict__ cq, const float* __restrict__ ck,
    const float* __restrict__ cv)
{
    __shared__ float sq[2][8], sk[2][8];
    int strip = blockIdx.x;
    int row0 = strip * TLc;
    int b = row0 >> 12;
    int l0 = row0 & 4095;
    int t = threadIdx.x;
    int p0 = t * 4;
    int h = p0 >> 8;
    int d0 = p0 & 255;
    int warp = t >> 5, lane = t & 31;

    float wq[16], wk[16], wv[16];
    #pragma unroll
    for (int i=0;i<4;i++){
        *(float4*)&wq[i*4]  = *(const float4*)&cq[(p0+i)*4];
        *(float4*)&wk[i*4]  = *(const float4*)&ck[(p0+i)*4];
        *(float4*)&wv[i*4]  = *(const float4*)&cv[(p0+i)*4];
    }

    #pragma unroll 1
    for (int it = 0; it < TLc; ++it){
        int pp = it & 1;
        int l = l0 + it;
        size_t base = ((size_t)(b*4096 + l))*1024 + p0;

        // taps j=0..3 correspond to rows l-3+j; OOB rows are zero.
        float q4[4] = {0,0,0,0}, k4[4] = {0,0,0,0}, v4[4] = {0,0,0,0};
        #pragma unroll
        for (int j = 0; j < 4; j++){
            int lj = l - 3 + j;
            if (lj < 0) continue;
            size_t rb = base + (size_t)(j - 3) * 1024;
            float tq[4], tk[4], tv[4];
            *(float4*)tq = ld4h(&g_qlinh[rb]);
            *(float4*)tk = ld4h(&g_klinh[rb]);
            *(float4*)tv = ld4h(&g_vlinh[rb]);
            #pragma unroll
            for (int ii=0;ii<4;ii++){
                q4[ii] = fmaf(wq[ii*4+j], tq[ii], q4[ii]);
                k4[ii] = fmaf(wk[ii*4+j], tk[ii], k4[ii]);
                v4[ii] = fmaf(wv[ii*4+j], tv[ii], v4[ii]);
            }
        }
        #pragma unroll
        for (int ii=0;ii<4;ii++){
            q4[ii] = q4[ii] / (1.f + expf(-q4[ii]));
            k4[ii] = k4[ii] / (1.f + expf(-k4[ii]));
            v4[ii] = v4[ii] / (1.f + expf(-v4[ii]));
        }

        float qs = q4[0]*q4[0]+q4[1]*q4[1]+q4[2]*q4[2]+q4[3]*q4[3];
        float ks = k4[0]*k4[0]+k4[1]*k4[1]+k4[2]*k4[2]+k4[3]*k4[3];
        #pragma unroll
        for (int o=16;o;o>>=1){
            qs += __shfl_xor_sync(0xffffffffu, qs, o);
            ks += __shfl_xor_sync(0xffffffffu, ks, o);
        }
        if (lane == 0){
            sq[pp][warp] = qs; sk[pp][warp] = ks;
        }
        __syncthreads();
        float qsum = sq[pp][2*h] + sq[pp][2*h+1];
        float ksum = sk[pp][2*h] + sk[pp][2*h+1];
        float qi = rsqrtf(qsum) * 0.0625f;
        float ki = rsqrtf(ksum);
        size_t ob = (((size_t)(b*4 + h))*4096 + l)*256 + d0;
        uint32_t h0,l0b,h1,l1;
        split2h(q4[0]*qi, q4[1]*qi, h0, l0b);
        split2h(q4[2]*qi, q4[3]*qi, h1, l1);
        { uint2 hh = {h0,h1}, ll = {l0b,l1};
          *(uint2*)&g_Qbh[ob] = hh; *(uint2*)&g_Qbl[ob] = ll; }
        split2h(k4[0]*ki, k4[1]*ki, h0, l0b);
        split2h(k4[2]*ki, k4[3]*ki, h1, l1);
        { uint2 hh = {h0,h1}, ll = {l0b,l1};
          *(uint2*)&g_Kbh[ob] = hh; *(uint2*)&g_Kbl[ob] = ll; }
        { uint2 hh = {pack2h(v4[0], v4[1]), pack2h(v4[2], v4[3])};
          *(uint2*)&g_Vbh[ob] = hh; }
        // ping-pong buffers: no trailing barrier
    }
}

// =====================================================================
// Tensorized chunk precompute, fp16 2-pass (A keeps lo, B hi-only).
// =====================================================================
#define PP_KQH 0
#define PP_KQL 67584
#define PP_VH  135168
#define PP_BYTES 202752
#define PP_ASH 33792
#define PP_TSH 50688
#define PP_TBH 101376
#define PP_TBL 110592
#define PP_SCR 119808

__global__ __launch_bounds__(256) void prep_kernel()
{
    extern __shared__ char smc[];
    uint32_t sb = smem_u32(smc);
    __shared__ float bsh[64];
    float* Ash = (float*)(smc + PP_ASH);
    float* Tsh = (float*)(smc + PP_TSH);
    float* SCR = (float*)(smc + PP_SCR);

    int ch = blockIdx.x, bh = blockIdx.y;
    int tid = threadIdx.x, lane = tid & 31, wid = tid >> 5;
    size_t rowbase = (size_t)bh*Ln + ch*Cn;
    size_t gbase = ((size_t)(bh*NCn + ch))*4096;

    #pragma unroll
    for (int i=0;i<16;i++){
        int flat = tid + i*256;
        int r = flat >> 5, cc = flat & 31;
        const __half* ph = (r < 64) ? g_Kbh : g_Qbh;
        const __half* pl = (r < 64) ? g_Kbl : g_Qbl;
        size_t src = (rowbase + (r & 63))*256 + cc*8;
        cp_async16(sb + PP_KQH + (uint32_t)(r*528 + cc*16), ph + src);
        cp_async16(sb + PP_KQL + (uint32_t)(r*528 + cc*16), pl + src);
    }
    #pragma unroll
    for (int i=0;i<8;i++){
        int flat = tid + i*256;
        int r = flat >> 5, cc = flat & 31;
        size_t src = (rowbase + r)*256 + cc*8;
        cp_async16(sb + PP_VH + (uint32_t)(r*528 + cc*16), g_Vbh + src);
    }
    if (tid < 64) bsh[tid] = g_beta[(size_t)bh*Ln + ch*Cn + tid];
    cp_commit(); cp_wait<0>(); __syncthreads();

    float acc[4][2][4];
    #pragma unroll
    for (int nb=0;nb<4;nb++)
        #pragma unroll
        for (int f=0;f<2;f++)
            #pragma unroll
            for (int q=0;q<4;q++) acc[nb][f][q] = 0.f;

    uint32_t aOffH = PP_KQH + (uint32_t)((wid*16 + (lane & 15))*528 + ((lane >> 4) << 4));
    uint32_t aOffL = aOffH + (PP_KQL - PP_KQH);
    uint32_t bLane = (uint32_t)(((lane & 7) + ((lane >> 4) << 3))*528 + (((lane >> 3) & 1) << 4));

    for (int ks = 0; ks < 16; ++ks){
        uint32_t off = (uint32_t)(ks*32);
        uint32_t ah[4], al[4];
        ldsm_x4(ah, sb + aOffH + off);
        ldsm_x4(al, sb + aOffL + off);
        #pragma unroll
        for (int nb = 0; nb < 4; nb++){
            uint32_t ba = sb + PP_KQH + bLane + (uint32_t)(nb*16*528) + off;
            uint32_t bhf[4];
            ldsm_x4(bhf, ba);
            mma16816_hf32(acc[nb][0], ah, bhf[0], bhf[1]);
            mma16816_hf32(acc[nb][0], al, bhf[0], bhf[1]);
            mma16816_hf32(acc[nb][1], ah, bhf[2], bhf[3]);
            mma16816_hf32(acc[nb][1], al, bhf[2], bhf[3]);
        }
    }
    __syncthreads();

    int r0 = wid*16 + (lane >> 2);
    if (wid < 4){
        #pragma unroll
        for (int nb = 0; nb < 4; nb++)
            #pragma unroll
            for (int f = 0; f < 2; f++){
                int c = nb*16 + f*8 + (lane & 3)*2;
                float vals[2][2] = {{acc[nb][f][0], acc[nb][f][1]},
                                    {acc[nb][f][2], acc[nb][f][3]}};
                #pragma unroll
                for (int hr = 0; hr < 2; hr++){
                    int rr = r0 + hr*8;
                    #pragma unroll
                    for (int jc = 0; jc < 2; jc++){
                        int cc = c + jc;
                        if (rr > cc)      Ash[rr*66 + cc] = bsh[rr]*vals[hr][jc];
                        else if (rr == cc) Ash[rr*66 + cc] = 1.f;
                    }
                }
            }
    } else {
        int gr0 = r0 - 64;
        #pragma unroll
        for (int nb = 0; nb < 4; nb++)
            #pragma unroll
            for (int f = 0; f < 2; f++){
                int c = nb*16 + f*8 + (lane & 3)*2;
                #pragma unroll
                for (int hr = 0; hr < 2; hr++){
                    int gr = gr0 + hr*8;
                    float m0 = (c   <= gr) ? acc[nb][f][hr*2+0] : 0.f;
                    float m1 = (c+1 <= gr) ? acc[nb][f][hr*2+1] : 0.f;
                    uint32_t ho, lo;
                    split2h(m0, m1, ho, lo);
                    *(uint32_t*)&g_Gbh[gbase + gr*64 + c] = ho;
                    *(uint32_t*)&g_Gbl[gbase + gr*64 + c] = lo;
                }
            }
    }
    for (int f = tid; f < 64*66; f += 256) Tsh[f] = 0.f;
    __syncthreads();

    if (tid < 64){
        int Bb = tid >> 4, jj = tid & 15, base = Bb*16;
        Tsh[(base+jj)*66 + base+jj] = 1.f;
        for (int i = jj+1; i < 16; i++){
            float s = 0.f;
            for (int m = jj; m < i; m++)
                s = fmaf(Ash[(base+i)*66 + base+m], Tsh[(base+m)*66 + base+jj], s);
            Tsh[(base+i)*66 + base+jj] = -s;
        }
    }
    __syncthreads();

    {
        int ii = tid >> 4, jj = tid & 15;
        for (int I = 1; I < 4; I++){
            for (int J = 0; J < I; J++){
                float s = 0.f;
                for (int K = J; K < I; K++){
                    #pragma unroll
                    for (int m = 0; m < 16; m++)
                        s = fmaf(Ash[(I*16+ii)*66 + K*16+m], Tsh[(K*16+m)*66 + J*16+jj], s);
                }
                SCR[(J*16+ii)*17 + jj] = s;
            }
            __syncthreads();
            for (int J = 0; J < I; J++){
                float v = 0.f;
                #pragma unroll
                for (int m = 0; m < 16; m++)
                    v = fmaf(Tsh[(I*16+ii)*66 + I*16+m], SCR[(J*16+m)*17 + jj], v);
                Tsh[(I*16+ii)*66 + J*16+jj] = -v;
            }
            __syncthreads();
        }
    }

    {
        int r = tid >> 2;
        int cb = (tid & 3)*16;
        #pragma unroll
        for (int p = 0; p < 8; p++){
            int c = cb + p*2;
            float v0 = Tsh[r*66 + c]   * bsh[c];
            float v1 = Tsh[r*66 + c+1] * bsh[c+1];
            uint32_t ho, lo;
            split2h(v0, v1, ho, lo);
            *(uint32_t*)(smc + PP_TBH + r*144 + c*2) = ho;
            *(uint32_t*)(smc + PP_TBL + r*144 + c*2) = lo;
        }
    }
    __syncthreads();

    {
        int wm = wid & 3, sel = wid >> 2;
        uint32_t bBase = sel ? PP_VH : PP_KQH;
        uint32_t aOff2 = PP_TBH + (uint32_t)((wm*16 + (lane & 15))*144 + ((lane >> 4) << 4));
        uint32_t bl2 = (uint32_t)(((((lane >> 3) & 1)*8) + (lane & 7))*528 + ((lane >> 4) << 4));

        for (int nc = 0; nc < 4; nc++){
            float a2[8][4];
            #pragma unroll
            for (int i=0;i<8;i++)
                #pragma unroll
                for (int q=0;q<4;q++) a2[i][q] = 0.f;
            #pragma unroll
            for (int ks = 0; ks < 4; ks++){
                uint32_t ath[4], atl[4];
                ldsm_x4(ath, sb + aOff2 + (uint32_t)(ks*32));
                ldsm_x4(atl, sb + aOff2 + (uint32_t)(PP_TBL - PP_TBH) + (uint32_t)(ks*32));
                #pragma unroll
                for (int nf = 0; nf < 4; nf++){
                    uint32_t ba = sb + bBase + bl2 + (uint32_t)(ks*16*528 + (nc*64 + nf*16)*2);
                    uint32_t kh[4];
                    ldsm_x4_t(kh, ba);
                    mma16816_hf32(a2[nf*2],   ath, kh[0], kh[1]);
                    mma16816_hf32(a2[nf*2],   atl, kh[0], kh[1]);
                    mma16816_hf32(a2[nf*2+1], ath, kh[2], kh[3]);
                    mma16816_hf32(a2[nf*2+1], atl, kh[2], kh[3]);
                }
            }
            int rr = wm*16 + (lane >> 2);
            #pragma unroll
            for (int nf = 0; nf < 4; nf++)
                #pragma unroll
                for (int hf = 0; hf < 2; hf++){
                    int d = nc*64 + nf*16 + hf*8 + (lane & 3)*2;
                    int idx = nf*2 + hf;
                    if (sel == 0){
                        uint32_t ho, lo;
                        split2h(a2[idx][0], a2[idx][1], ho, lo);
                        *(uint32_t*)&g_Wbh[(rowbase + rr)*256 + d] = ho;
                        *(uint32_t*)&g_Wbl[(rowbase + rr)*256 + d] = lo;
                        split2h(a2[idx][2], a2[idx][3], ho, lo);
                        *(uint32_t*)&g_Wbh[(rowbase + rr + 8)*256 + d] = ho;
                        *(uint32_t*)&g_Wbl[(rowbase + rr + 8)*256 + d] = lo;
                    } else {
                        float2 v0 = {a2[idx][0], a2[idx][1]};
                        float2 v1 = {a2[idx][2], a2[idx][3]};
                        *(float2*)&g_U[(rowbase + rr)*256 + d]     = v0;
                        *(float2*)&g_U[(rowbase + rr + 8)*256 + d] = v1;
                    }
                }
        }
    }
}

// =====================================================================
// Sequential chunk scan, fp16 2-pass everywhere.
// =====================================================================
#define OFF_S   0
#define OFF_SH  33280
#define OFF_WQH 67072
#define OFF_WQL 134656
#define OFF_KBH OFF_WQH
#define OFF_GBH 202240
#define OFF_GBL 211456
#define OFF_MTH 220672
#define OFF_MTL 225280
#define SCAN_SMEM_BYTES 229888
#define SPITCH 528
#define MPITCH 144

__device__ __forceinline__ void store_mt(char* smc, int d, int c, float m){
    __half h = __float2half_rn(m);
    float lo = m - __half2float(h);
    *(__half*)(smc + OFF_MTH + d*MPITCH + c*2) = h;
    *(__half*)(smc + OFF_MTL + d*MPITCH + c*2) = __float2half_rn(lo);
}

__global__ __launch_bounds__(256) void scan_kernel(float* __restrict__ Sout)
{
    extern __shared__ char smc[];
    uint32_t sb = smem_u32(smc);
    float* Ssh = (float*)(smc + OFF_S);

    int bx = blockIdx.x;
    int bh = bx >> 3;
    int dt = bx & 7;
    int d0 = dt * 32;
    int tid = threadIdx.x;
    int lane = tid & 31, wid = tid >> 5;

    for (int f = tid; f < 32*260; f += 256) Ssh[f] = 0.f;
    __syncthreads();

    uint32_t aOffH = OFF_WQH + (uint32_t)(wid*16 + (lane & 15))*SPITCH + ((lane >> 4) << 4);
    uint32_t aOffL = aOffH + (OFF_WQL - OFF_WQH);
    uint32_t bRowOff = (uint32_t)((lane & 7) + ((lane >> 4) << 3))*SPITCH + (((lane >> 3) & 1) << 4);

    for (int ch = 0; ch < NCn; ++ch){
        size_t rowbase = (size_t)bh*Ln + ch*Cn;
        size_t gbaseE = ((size_t)(bh*NCn + ch))*(Cn*Cn);

        #pragma unroll
        for (int i = 0; i < 16; i++){
            int flat = tid + i*256;
            int r = flat >> 5;
            int cch = flat & 31;
            size_t src = (r < 64) ? (rowbase + r)*256 + cch*8
                                  : (rowbase + r - 64)*256 + cch*8;
            const __half* ph = (r < 64) ? g_Wbh : g_Qbh;
            const __half* pl = (r < 64) ? g_Wbl : g_Qbl;
            cp_async16(sb + OFF_WQH + (uint32_t)(r*SPITCH + cch*16), ph + src);
            cp_async16(sb + OFF_WQL + (uint32_t)(r*SPITCH + cch*16), pl + src);
        }
        #pragma unroll
        for (int i = 0; i < 4; i++){
            int flat = tid + i*256;
            int half2i = flat >> 9;
            int idx = flat & 511;
            int r = idx >> 3, cch = idx & 7;
            const __half* pg = half2i ? g_Gbl : g_Gbh;
            uint32_t dstoff = half2i ? OFF_GBL : OFF_GBH;
            cp_async16(sb + dstoff + (uint32_t)(r*MPITCH + cch*16), pg + gbaseE + r*64 + cch*8);
        }
        cp_commit();

        {
            int r = tid >> 3;
            int cc = (tid & 7) * 32;
            #pragma unroll
            for (int j = 0; j < 8; j++){
                float4 v = *(float4*)&Ssh[r*260 + cc + j*4];
                uint2 hh = {pack2h(v.x, v.y), pack2h(v.z, v.w)};
                *(uint2*)(smc + OFF_SH + r*SPITCH + cc*2 + j*8) = hh;
            }
        }
        cp_wait<0>();
        __syncthreads();

        float acc[4][4];
        #pragma unroll
        for (int i=0;i<4;i++)
            #pragma unroll
            for (int q=0;q<4;q++) acc[i][q] = 0.f;

        for (int ks = 0; ks < 16; ++ks){
            uint32_t off = (uint32_t)(ks*32);
            uint32_t ah[4], al[4], b0h[4], b1h[4];
            ldsm_x4(ah, sb + aOffH + off);
            ldsm_x4(al, sb + aOffL + off);
            ldsm_x4(b0h, sb + OFF_SH + bRowOff + off);
            ldsm_x4(b1h, sb + OFF_SH + 16*SPITCH + bRowOff + off);
            mma16816_hf32(acc[0], ah, b0h[0], b0h[1]);
            mma16816_hf32(acc[0], al, b0h[0], b0h[1]);
            mma16816_hf32(acc[1], ah, b0h[2], b0h[3]);
            mma16816_hf32(acc[1], al, b0h[2], b0h[3]);
            mma16816_hf32(acc[2], ah, b1h[0], b1h[1]);
            mma16816_hf32(acc[2], al, b1h[0], b1h[1]);
            mma16816_hf32(acc[3], ah, b1h[2], b1h[3]);
            mma16816_hf32(acc[3], al, b1h[2], b1h[3]);
        }

        int crow = wid*16 + (lane >> 2);
        if (wid < 4){
            #pragma unroll
            for (int in = 0; in < 4; in++){
                int d = in*8 + (lane & 3)*2;
                float2 u0 = *(const float2*)&g_U[(rowbase + crow)*256 + d0 + d];
                float2 u1 = *(const float2*)&g_U[(rowbase + crow + 8)*256 + d0 + d];
                store_mt(smc, d,   crow,     u0.x - acc[in][0]);
                store_mt(smc, d+1, crow,     u0.y - acc[in][1]);
                store_mt(smc, d,   crow + 8, u1.x - acc[in][2]);
                store_mt(smc, d+1, crow + 8, u1.y - acc[in][3]);
            }
        } else {
            int c = crow - 64;
            #pragma unroll
            for (int in = 0; in < 4; in++){
                int d = in*8 + (lane & 3)*2;
                float2 v0 = {acc[in][0], acc[in][1]};
                float2 v1 = {acc[in][2], acc[in][3]};
                *(float2*)&g_o[(rowbase + c)*256 + d0 + d]     = v0;
                *(float2*)&g_o[(rowbase + c + 8)*256 + d0 + d] = v1;
            }
        }
        __syncthreads();

        #pragma unroll
        for (int i = 0; i < 8; i++){
            int flat = tid + i*256;
            int r = flat >> 5, cch = flat & 31;
            cp_async16(sb + OFF_KBH + (uint32_t)(r*SPITCH + cch*16),
                       g_Kbh + (rowbase + r)*256 + cch*8);
        }
        cp_commit();

        {
            int wm2 = wid >> 1, wn2 = wid & 1;
            uint32_t aOff2 = sb + OFF_GBH + (uint32_t)((wm2*16 + (lane & 15))*MPITCH + ((lane >> 4) << 4));
            uint32_t bOff2 = sb + OFF_MTH + (uint32_t)((wn2*16 + (lane & 7) + ((lane >> 4) << 3))*MPITCH + (((lane >> 3) & 1) << 4));
            float a2[2][4];
            #pragma unroll
            for (int f=0;f<2;f++)
                #pragma unroll
                for (int q=0;q<4;q++) a2[f][q] = 0.f;
            #pragma unroll
            for (int ks = 0; ks < 4; ++ks){
                uint32_t off = (uint32_t)(ks*32);
                uint32_t gah[4], gal[4], mbh[4];
                ldsm_x4(gah, aOff2 + off);
                ldsm_x4(gal, aOff2 + (OFF_GBL - OFF_GBH) + off);
                ldsm_x4(mbh, bOff2 + off);
                #pragma unroll
                for (int f = 0; f < 2; f++){
                    int j = f*2;
                    mma16816_hf32(a2[f], gah, mbh[j], mbh[j+1]);
                    mma16816_hf32(a2[f], gal, mbh[j], mbh[j+1]);
                }
            }
            int c = wm2*16 + (lane >> 2);
            #pragma unroll
            for (int f = 0; f < 2; f++){
                int d = wn2*16 + f*8 + (lane & 3)*2;
                float2 t0 = *(const float2*)&g_o[(rowbase + c)*256 + d0 + d];
                float2 t1 = *(const float2*)&g_o[(rowbase + c + 8)*256 + d0 + d];
                t0.x += a2[f][0]; t0.y += a2[f][1];
                t1.x += a2[f][2]; t1.y += a2[f][3];
                *(float2*)&g_o[(rowbase + c)*256 + d0 + d]     = t0;
                *(float2*)&g_o[(rowbase + c + 8)*256 + d0 + d] = t1;
            }
        }
        cp_wait<0>();
        __syncthreads();

        {
            int wm3 = wid >> 2, wn3 = wid & 3;
            uint32_t aOff3 = sb + OFF_MTH + (uint32_t)((wm3*16 + (lane & 15))*MPITCH + ((lane >> 4) << 4));
            uint32_t bLane = (uint32_t)((((lane >> 3) & 1)*8 + (lane & 7))*SPITCH + ((lane >> 4) << 4));
            float a3[8][4];
            #pragma unroll
            for (int i=0;i<8;i++)
                #pragma unroll
                for (int q=0;q<4;q++) a3[i][q] = 0.f;
            #pragma unroll
            for (int ks = 0; ks < 4; ++ks){
                uint32_t mtH[4], mtL[4];
                ldsm_x4(mtH, aOff3 + (uint32_t)(ks*32));
                ldsm_x4(mtL, aOff3 + (OFF_MTL - OFF_MTH) + (uint32_t)(ks*32));
                #pragma unroll
                for (int nf = 0; nf < 4; nf++){
                    int n0 = wn3*64 + nf*16;
                    uint32_t ba = sb + OFF_KBH + bLane + (uint32_t)(ks*16*SPITCH + n0*2);
                    uint32_t kh[4];
                    ldsm_x4_t(kh, ba);
                    mma16816_hf32(a3[nf*2],   mtH, kh[0], kh[1]);
                    mma16816_hf32(a3[nf*2],   mtL, kh[0], kh[1]);
                    mma16816_hf32(a3[nf*2+1], mtH, kh[2], kh[3]);
                    mma16816_hf32(a3[nf*2+1], mtL, kh[2], kh[3]);
                }
            }
            int d = wm3*16 + (lane >> 2);
            #pragma unroll
            for (int nf = 0; nf < 4; nf++){
                #pragma unroll
                for (int hf = 0; hf < 2; hf++){
                    int e = wn3*64 + nf*16 + hf*8 + (lane & 3)*2;
                    int idx = nf*2 + hf;
                    Ssh[d*260 + e]         += a3[idx][0];
                    Ssh[d*260 + e + 1]     += a3[idx][1];
                    Ssh[(d+8)*260 + e]     += a3[idx][2];
                    Ssh[(d+8)*260 + e + 1] += a3[idx][3];
                }
            }
        }
        __syncthreads();
    }

    if (Sout){
        for (int f = tid; f < 32*256; f += 256){
            int dr = f >> 8, e = f & 255;
            Sout[((size_t)bh*256 + d0 + dr)*256 + e] = Ssh[dr*260 + e];
        }
    }
}

// =====================================================================
// RMSNorm + regather to (b,l,p) as fp16 hi/lo split (for final GEMM).
// =====================================================================
__global__ __launch_bounds__(256) void rms_kernel(const float* __restrict__ rmsw)
{
    int tid = threadIdx.x;
    int w = tid >> 5, lane = tid & 31;
    size_t r = (size_t)blockIdx.x * 8 + w;
    int bh = (int)(r >> 12);
    int l  = (int)(r & 4095);
    int b = bh >> 2, h = bh & 3;
    const float* op = &g_o[r*256];
    float4 v0 = *(const float4*)&op[lane*4];
    float4 v1 = *(const float4*)&op[128 + lane*4];
    float ss = v0.x*v0.x+v0.y*v0.y+v0.z*v0.z+v0.w*v0.w
             + v1.x*v1.x+v1.y*v1.y+v1.z*v1.z+v1.w*v1.w;
    #pragma unroll
    for (int o=16;o;o>>=1) ss += __shfl_xor_sync(0xffffffffu, ss, o);
    float scale = rsqrtf(ss * (1.f/256.f) + 1e-5f);
    float4 w0 = *(const float4*)&rmsw[lane*4];
    float4 w1 = *(const float4*)&rmsw[128 + lane*4];
    float o0[4] = {v0.x*scale*w0.x, v0.y*scale*w0.y, v0.z*scale*w0.z, v0.w*scale*w0.w};
    float o1[4] = {v1.x*scale*w1.x, v1.y*scale*w1.y, v1.z*scale*w1.z, v1.w*scale*w1.w};
    size_t obase = ((size_t)(b*4096 + l))*1024 + h*256;
    uint32_t h0,l0,h1,l1;
    split2h(o0[0], o0[1], h0, l0);
    split2h(o0[2], o0[3], h1, l1);
    uint2 hh = {h0,h1}, ll = {l0,l1};
    *(uint2*)&g_onh[obase + lane*4] = hh;
    *(uint2*)&g_onl[obase + lane*4] = ll;
    split2h(o1[0], o1[1], h0, l0);
    split2h(o1[2], o1[3], h1, l1);
    uint2 hh2 = {h0,h1}, ll2 = {l0,l1};
    *(uint2*)&g_onh[obase + 128 + lane*4] = hh2;
    *(uint2*)&g_onl[obase + 128 + lane*4] = ll2;
}

// =====================================================================
extern "C" void kernel_launch(void* const* d_in, const int* in_sizes, int n_in,
                              void* d_out, int out_size)
{
    const float* x   = (const float*)d_in[0];
    const float* Wq  = (const float*)d_in[1];
    const float* Wk  = (const float*)d_in[2];
    const float* Wv  = (const float*)d_in[3];
    const float* Wb  = (const float*)d_in[4];
    const float* cq  = (const float*)d_in[5];
    const float* ck  = (const float*)d_in[6];
    const float* cv  = (const float*)d_in[7];
    const float* rw  = (const float*)d_in[8];
    const float* Wo  = (const float*)d_in[9];
    float* out = (float*)d_out;

    __half *qlin, *klin, *vlin;
    __half *xh, *xl, *onh, *onl, *wT;
    cudaGetSymbolAddress((void**)&qlin, g_qlinh);
    cudaGetSymbolAddress((void**)&klin, g_klinh);
    cudaGetSymbolAddress((void**)&vlin, g_vlinh);
    cudaGetSymbolAddress((void**)&xh,  g_xh);
    cudaGetSymbolAddress((void**)&xl,  g_xl);
    cudaGetSymbolAddress((void**)&onh, g_onh);
    cudaGetSymbolAddress((void**)&onl, g_onl);
    cudaGetSymbolAddress((void**)&wT,  g_wT);
    const size_t WSZ = 1024*1024;
    __half *wqh = wT;
    __half *wkh = wT + 2*WSZ;
    __half *wvh = wT + 4*WSZ;
    __half *woh = wT + 6*WSZ;

    cudaFuncSetAttribute(prep_kernel, cudaFuncAttributeMaxDynamicSharedMemorySize, PP_BYTES);
    cudaFuncSetAttribute(scan_kernel, cudaFuncAttributeMaxDynamicSharedMemorySize, SCAN_SMEM_BYTES);
    cudaFuncSetAttribute(gemm_qkv,    cudaFuncAttributeMaxDynamicSharedMemorySize, GEMM_SMEM);
    cudaFuncSetAttribute(gemm_out,    cudaFuncAttributeMaxDynamicSharedMemorySize, GEMM_SMEM);

    // merged weight transpose (one launch) + x split (also computes beta)
    wsplit_kernel<<<dim3(32, 32, 4), 256>>>(Wq, Wk, Wv, Wo, wqh, wkh, wvh, woh);
    xsplit_kernel<<<ROWS, 256>>>(x, xh, xl, Wb);

    // merged QKV projection (fp16 out)
    gemm_qkv<<<dim3(8, 128, 3), 256, GEMM_SMEM>>>(xh, xl, wqh, wkh, wvh,
                                                  qlin, klin, vlin);

    conv_kernel<<<ROWS/TLc, 256>>>(cq, ck, cv);

    prep_kernel<<<dim3(NCn, BHn), 256, PP_BYTES>>>();

    float* Sout = (out_size >= ELEMS + BHn*Dn*Dn) ? (out + ELEMS) : nullptr;
    scan_kernel<<<128, 256, SCAN_SMEM_BYTES>>>(Sout);

    rms_kernel<<<(BHn*Ln)/8, 256>>>(rw);

    gemm_out<<<dim3(8, 128), 256, GEMM_SMEM>>>(onh, onl, woh, out);
}